// round 5
// baseline (speedup 1.0000x reference)
#include <cuda_runtime.h>

// ---------------------------------------------------------------------------
// EarthAttention3D  (Bw=256, N=144, DIM=384, H=12, HD=32)
// Stage A: QKV GEMM  (36864x384 @ 384x1152) -> Q(scaled),K,V in (b,h,n,d)
// Stage B: per-(b,h) attention: S = QK^T + bias_gather + mask; softmax; PV
// Stage C: out GEMM  (36864x384 @ 384x384) + bias -> d_out
// All inner products use Blackwell packed fma.rn.f32x2 (2 fp32 FMA / issue).
// ---------------------------------------------------------------------------

#define BW_    256
#define NT_    144
#define DIM_   384
#define HEADS_ 12
#define HD_    32
#define NN_    (NT_*NT_)      // 20736
#define TOW_   32
#define MTOT_  (BW_*NT_)      // 36864

// scratch (device globals; allocation in kernel_launch is forbidden)
__device__ float g_q[(size_t)BW_*HEADS_*NT_*HD_];
__device__ float g_k[(size_t)BW_*HEADS_*NT_*HD_];
__device__ float g_v[(size_t)BW_*HEADS_*NT_*HD_];
__device__ float g_att[(size_t)BW_*NT_*DIM_];

// ---- packed f32x2 helpers (sm_103a) ---------------------------------------
__device__ __forceinline__ unsigned long long pack2(float x) {
    unsigned long long r;
    asm("mov.b64 %0, {%1, %1};" : "=l"(r) : "f"(x));
    return r;
}
__device__ __forceinline__ void fma2(unsigned long long& d,
                                     unsigned long long a,
                                     unsigned long long b) {
    asm("fma.rn.f32x2 %0, %1, %2, %0;" : "+l"(d) : "l"(a), "l"(b));
}
__device__ __forceinline__ float lo2(unsigned long long v) {
    return __uint_as_float((unsigned)v);
}
__device__ __forceinline__ float hi2(unsigned long long v) {
    return __uint_as_float((unsigned)(v >> 32));
}

// ---------------------------------------------------------------------------
// 128x128x8 register-tiled SGEMM, 256 threads, 8x8 microtile per thread.
// Double-buffered smem + register prefetch: one barrier per K-tile.
// QKV=true : C = x @ w_qkv + b_qkv, scattered into g_q (scaled), g_k, g_v
// QKV=false: C = g_att @ w_out + b_out -> out
// ---------------------------------------------------------------------------
template<int NOUT, bool QKV>
__global__ __launch_bounds__(256) void sgemm128(const float* __restrict__ A_in,
                                                const float* __restrict__ Bm,
                                                const float* __restrict__ bias,
                                                float* __restrict__ out)
{
    __shared__ float As[2][8][132];
    __shared__ float Bs[2][8][132];
    const int K = DIM_;
    const float* A = QKV ? A_in : g_att;

    const int bm = blockIdx.y * 128;
    const int bn = blockIdx.x * 128;
    const int tid = threadIdx.x;
    const int tx = tid & 15, ty = tid >> 4;

    unsigned long long acc2[8][4];
#pragma unroll
    for (int i = 0; i < 8; i++)
#pragma unroll
        for (int j = 0; j < 4; j++) acc2[i][j] = 0ull;

    const int arow  = tid >> 1;
    const int acol4 = (tid & 1) * 4;
    const int brow  = tid >> 5;
    const int bcol4 = (tid & 31) * 4;

    const float* Aptr = &A[(size_t)(bm + arow) * K + acol4];
    const float* Bptr = &Bm[(size_t)brow * NOUT + bn + bcol4];

    // prologue: tile 0 -> buffer 0
    {
        float4 av = *(const float4*)Aptr;
        float4 bv = *(const float4*)Bptr;
        As[0][acol4 + 0][arow] = av.x;
        As[0][acol4 + 1][arow] = av.y;
        As[0][acol4 + 2][arow] = av.z;
        As[0][acol4 + 3][arow] = av.w;
        *(float4*)&Bs[0][brow][bcol4] = bv;
    }
    __syncthreads();

    int buf = 0;
    for (int k0 = 0; k0 < K; k0 += 8) {
        // prefetch next tile into registers while computing on current smem
        float4 av2, bv2;
        const bool more = (k0 + 8 < K);
        if (more) {
            av2 = *(const float4*)(Aptr + k0 + 8);
            bv2 = *(const float4*)(Bptr + (size_t)(k0 + 8) * NOUT);
        }
#pragma unroll
        for (int k = 0; k < 8; k++) {
            float4 a0 = *(const float4*)&As[buf][k][ty * 4];
            float4 a1 = *(const float4*)&As[buf][k][64 + ty * 4];
            ulonglong2 b01 = *(const ulonglong2*)&Bs[buf][k][tx * 4];
            ulonglong2 b23 = *(const ulonglong2*)&Bs[buf][k][64 + tx * 4];
            unsigned long long ap[8];
            ap[0] = pack2(a0.x); ap[1] = pack2(a0.y);
            ap[2] = pack2(a0.z); ap[3] = pack2(a0.w);
            ap[4] = pack2(a1.x); ap[5] = pack2(a1.y);
            ap[6] = pack2(a1.z); ap[7] = pack2(a1.w);
            unsigned long long bp[4] = {b01.x, b01.y, b23.x, b23.y};
#pragma unroll
            for (int ii = 0; ii < 8; ii++) {
                fma2(acc2[ii][0], ap[ii], bp[0]);
                fma2(acc2[ii][1], ap[ii], bp[1]);
                fma2(acc2[ii][2], ap[ii], bp[2]);
                fma2(acc2[ii][3], ap[ii], bp[3]);
            }
        }
        if (more) {
            int nb = buf ^ 1;
            As[nb][acol4 + 0][arow] = av2.x;
            As[nb][acol4 + 1][arow] = av2.y;
            As[nb][acol4 + 2][arow] = av2.z;
            As[nb][acol4 + 3][arow] = av2.w;
            *(float4*)&Bs[nb][brow][bcol4] = bv2;
        }
        __syncthreads();
        buf ^= 1;
    }

    // epilogue: acc2[ii][jp] holds column-pair jp -> 2 scalars each
#pragma unroll
    for (int ii = 0; ii < 8; ii++) {
        int r = bm + ((ii < 4) ? (ty * 4 + ii) : (60 + ty * 4 + ii));
        int bwin = r / NT_;
        int n    = r - bwin * NT_;
#pragma unroll
        for (int jp = 0; jp < 4; jp++) {
            float vals[2] = {lo2(acc2[ii][jp]), hi2(acc2[ii][jp])};
#pragma unroll
            for (int half = 0; half < 2; half++) {
                int c = bn + ((jp < 2) ? (tx * 4 + jp * 2 + half)
                                       : (64 + tx * 4 + (jp - 2) * 2 + half));
                float v = vals[half] + bias[c];
                if (QKV) {
                    int part = c / DIM_;
                    int rem  = c - part * DIM_;
                    int h = rem >> 5;
                    int d = rem & 31;
                    size_t idx = (((size_t)bwin * HEADS_ + h) * NT_ + n) * HD_ + d;
                    if (part == 0)      g_q[idx] = v * 0.17677669529663687f; // 1/sqrt(32)
                    else if (part == 1) g_k[idx] = v;
                    else                g_v[idx] = v;
                } else {
                    out[(size_t)r * NOUT + c] = v;
                }
            }
        }
    }
}

// ---------------------------------------------------------------------------
// Fused attention: one CTA per (window b, head h). 512 threads (16 warps)
// for latency hiding — smem already caps occupancy at 1 CTA/SM.
// smem: Qt[32][148] (transposed), Kt[32][148], V[144][32], S[144][149]
// ---------------------------------------------------------------------------
#define ATTN_THREADS 512
#define QT_STRIDE 148
#define S_STRIDE  149
#define ATTN_SMEM_FLOATS (32*QT_STRIDE*2 + NT_*HD_ + NT_*S_STRIDE)
#define ATTN_SMEM_BYTES  (ATTN_SMEM_FLOATS * 4)

__global__ __launch_bounds__(ATTN_THREADS) void attn_kernel(const float* __restrict__ mask,
                                                            const float* __restrict__ bias_table,
                                                            const int*   __restrict__ pos_index)
{
    extern __shared__ float smem[];
    float* Qt = smem;                         // 32 x 148
    float* Kt = Qt + 32 * QT_STRIDE;          // 32 x 148
    float* Vs = Kt + 32 * QT_STRIDE;          // 144 x 32
    float* S  = Vs + NT_ * HD_;               // 144 x 149

    const int bh = blockIdx.x;
    const int b  = bh / HEADS_;
    const int h  = bh - b * HEADS_;
    const int tid = threadIdx.x;

    const float* Qg = g_q + (size_t)bh * NT_ * HD_;
    const float* Kg = g_k + (size_t)bh * NT_ * HD_;
    const float* Vg = g_v + (size_t)bh * NT_ * HD_;

    const int b5  = b >> 5;     // which tile repeat of position_index
    const int t32 = b & 31;     // type-of-window index into bias_table
    const int w   = b & 7;      // mask window
    const float* maskw = mask + (size_t)w * NN_;
    const float* btab  = bias_table + (size_t)t32 * HEADS_ + h;

    // load + transpose Q,K; V natural
    for (int idx = tid; idx < NT_ * HD_; idx += ATTN_THREADS) {
        int n = idx >> 5, d = idx & 31;
        Qt[d * QT_STRIDE + n] = Qg[idx];
        Kt[d * QT_STRIDE + n] = Kg[idx];
        Vs[idx] = Vg[idx];
    }
    __syncthreads();

    // --- scores: 36x36 grid of 4x4 tiles (q broadcast-packed, k natural pairs)
    for (int t = tid; t < 1296; t += ATTN_THREADS) {
        int i0 = (t / 36) * 4;
        int j0 = (t % 36) * 4;
        unsigned long long acc2[4][2];
#pragma unroll
        for (int r = 0; r < 4; r++) { acc2[r][0] = 0ull; acc2[r][1] = 0ull; }
#pragma unroll
        for (int d = 0; d < 32; d++) {
            float4 qa = *(const float4*)&Qt[d * QT_STRIDE + i0];
            ulonglong2 kb = *(const ulonglong2*)&Kt[d * QT_STRIDE + j0];
            unsigned long long q0 = pack2(qa.x), q1 = pack2(qa.y);
            unsigned long long q2 = pack2(qa.z), q3 = pack2(qa.w);
            fma2(acc2[0][0], q0, kb.x); fma2(acc2[0][1], q0, kb.y);
            fma2(acc2[1][0], q1, kb.x); fma2(acc2[1][1], q1, kb.y);
            fma2(acc2[2][0], q2, kb.x); fma2(acc2[2][1], q2, kb.y);
            fma2(acc2[3][0], q3, kb.x); fma2(acc2[3][1], q3, kb.y);
        }
#pragma unroll
        for (int r = 0; r < 4; r++) {
            int i = i0 + r;
            // (m*8 + b5) mod N^2  ==  ((i mod 18)*144 + j)*8 + b5   (N^2 = 2592*8)
            int im18 = i % 18;
            float sv[4] = {lo2(acc2[r][0]), hi2(acc2[r][0]),
                           lo2(acc2[r][1]), hi2(acc2[r][1])};
#pragma unroll
            for (int c = 0; c < 4; c++) {
                int j = j0 + c;
                int m = i * NT_ + j;
                int p = (im18 * NT_ + j) * 8 + b5;
                int row = pos_index[p];
                float bv = btab[(size_t)row * (TOW_ * HEADS_)];
                S[i * S_STRIDE + j] = sv[c] + bv + maskw[m];
            }
        }
    }
    __syncthreads();

    // --- softmax: 16 warps, 9 rows each ---
    const int warp = tid >> 5, lane = tid & 31;
    for (int i = warp; i < NT_; i += (ATTN_THREADS / 32)) {
        float* Srow = &S[i * S_STRIDE];
        float mx = -1e30f;
        for (int c = lane; c < NT_; c += 32) mx = fmaxf(mx, Srow[c]);
#pragma unroll
        for (int o = 16; o; o >>= 1) mx = fmaxf(mx, __shfl_xor_sync(0xffffffffu, mx, o));
        float sum = 0.f;
        for (int c = lane; c < NT_; c += 32) {
            float e = __expf(Srow[c] - mx);
            Srow[c] = e;
            sum += e;
        }
#pragma unroll
        for (int o = 16; o; o >>= 1) sum += __shfl_xor_sync(0xffffffffu, sum, o);
        float inv = 1.f / sum;
        for (int c = lane; c < NT_; c += 32) Srow[c] *= inv;
    }
    __syncthreads();

    // --- PV: out[i][d], 72 i-tiles x 8 d-tiles of 2x4 (p broadcast, v pairs) ---
    float* Og = g_att + (size_t)b * NT_ * DIM_ + h * HD_;
    for (int t = tid; t < 576; t += ATTN_THREADS) {
        int i0 = (t >> 3) * 2;
        int d0 = (t & 7) * 4;
        unsigned long long acc2[2][2];
        acc2[0][0] = 0ull; acc2[0][1] = 0ull;
        acc2[1][0] = 0ull; acc2[1][1] = 0ull;
        for (int j = 0; j < NT_; j++) {
            ulonglong2 vv = *(const ulonglong2*)&Vs[j * HD_ + d0];
            unsigned long long p0 = pack2(S[(i0 + 0) * S_STRIDE + j]);
            unsigned long long p1 = pack2(S[(i0 + 1) * S_STRIDE + j]);
            fma2(acc2[0][0], p0, vv.x); fma2(acc2[0][1], p0, vv.y);
            fma2(acc2[1][0], p1, vv.x); fma2(acc2[1][1], p1, vv.y);
        }
#pragma unroll
        for (int r = 0; r < 2; r++) {
            float4 o4 = make_float4(lo2(acc2[r][0]), hi2(acc2[r][0]),
                                    lo2(acc2[r][1]), hi2(acc2[r][1]));
            *(float4*)&Og[(size_t)(i0 + r) * DIM_ + d0] = o4;
        }
    }
}

// ---------------------------------------------------------------------------
extern "C" void kernel_launch(void* const* d_in, const int* in_sizes, int n_in,
                              void* d_out, int out_size)
{
    const float* x          = (const float*)d_in[0];
    const float* mask       = (const float*)d_in[1];
    const float* w_qkv      = (const float*)d_in[2];
    const float* b_qkv      = (const float*)d_in[3];
    const float* w_out      = (const float*)d_in[4];
    const float* b_out      = (const float*)d_in[5];
    const float* bias_table = (const float*)d_in[6];
    const int*   pos_index  = (const int*)d_in[7];
    float* out = (float*)d_out;

    // idempotent, deterministic: safe to call every launch (not a stream op)
    cudaFuncSetAttribute(attn_kernel, cudaFuncAttributeMaxDynamicSharedMemorySize,
                         ATTN_SMEM_BYTES);

    // Stage A: QKV projection
    sgemm128<3 * DIM_, true><<<dim3((3 * DIM_) / 128, MTOT_ / 128), 256>>>(
        x, w_qkv, b_qkv, nullptr);

    // Stage B: fused attention per (window, head)
    attn_kernel<<<BW_ * HEADS_, ATTN_THREADS, ATTN_SMEM_BYTES>>>(mask, bias_table, pos_index);

    // Stage C: output projection
    sgemm128<DIM_, false><<<dim3(DIM_ / 128, MTOT_ / 128), 256>>>(
        nullptr, w_out, b_out, out);
}

// round 7
// speedup vs baseline: 1.0270x; 1.0270x over previous
#include <cuda_runtime.h>

// ---------------------------------------------------------------------------
// EarthAttention3D  (Bw=256, N=144, DIM=384, H=12, HD=32)
// Stage A: QKV GEMM  (36864x384 @ 384x1152) -> Q(scaled),K,V in (b,h,n,d)
// Stage B: attention, 2 CTAs per (b,h) (i-halves of 72 rows):
//          bias plane deduped (depends only on (i mod 18, j)) and gathered
//          once into smem; S = QK^T + bias + mask; softmax; PV
// Stage C: out GEMM  (36864x384 @ 384x384) + bias -> d_out
// All inner products use Blackwell packed fma.rn.f32x2 (2 fp32 FMA / issue).
// A-tile stored in smem pre-duplicated as f32x2 pairs: no packs in mainloop.
// ---------------------------------------------------------------------------

#define BW_    256
#define NT_    144
#define DIM_   384
#define HEADS_ 12
#define HD_    32
#define NN_    (NT_*NT_)      // 20736
#define TOW_   32
#define MTOT_  (BW_*NT_)      // 36864

// scratch (device globals; allocation in kernel_launch is forbidden)
__device__ float g_q[(size_t)BW_*HEADS_*NT_*HD_];
__device__ float g_k[(size_t)BW_*HEADS_*NT_*HD_];
__device__ float g_v[(size_t)BW_*HEADS_*NT_*HD_];
__device__ float g_att[(size_t)BW_*NT_*DIM_];

// ---- packed f32x2 helpers (sm_103a) ---------------------------------------
__device__ __forceinline__ unsigned long long pack2(float x) {
    unsigned long long r;
    asm("mov.b64 %0, {%1, %1};" : "=l"(r) : "f"(x));
    return r;
}
__device__ __forceinline__ void fma2(unsigned long long& d,
                                     unsigned long long a,
                                     unsigned long long b) {
    asm("fma.rn.f32x2 %0, %1, %2, %0;" : "+l"(d) : "l"(a), "l"(b));
}
__device__ __forceinline__ float lo2(unsigned long long v) {
    return __uint_as_float((unsigned)v);
}
__device__ __forceinline__ float hi2(unsigned long long v) {
    return __uint_as_float((unsigned)(v >> 32));
}

// ---------------------------------------------------------------------------
// 128x128x8 register-tiled SGEMM, 256 threads, 8x8 microtile per thread.
// Double-buffered smem + register prefetch: one barrier per K-tile.
// As holds duplicated pairs: As[k][2r], As[k][2r+1] both = A[row r, k].
// QKV=true : C = x @ w_qkv + b_qkv, scattered into g_q (scaled), g_k, g_v
// QKV=false: C = g_att @ w_out + b_out -> out
// ---------------------------------------------------------------------------
#define AS_STRIDE 264   // 2*128 + 8 pad floats per k-row
template<int NOUT, bool QKV>
__global__ __launch_bounds__(256) void sgemm128(const float* __restrict__ A_in,
                                                const float* __restrict__ Bm,
                                                const float* __restrict__ bias,
                                                float* __restrict__ out)
{
    __shared__ float As[2][8][AS_STRIDE];
    __shared__ float Bs[2][8][132];
    const int K = DIM_;
    const float* A = QKV ? A_in : g_att;

    const int bm = blockIdx.y * 128;
    const int bn = blockIdx.x * 128;
    const int tid = threadIdx.x;
    const int tx = tid & 15, ty = tid >> 4;

    unsigned long long acc2[8][4];
#pragma unroll
    for (int i = 0; i < 8; i++)
#pragma unroll
        for (int j = 0; j < 4; j++) acc2[i][j] = 0ull;

    const int arow  = tid >> 1;
    const int acol4 = (tid & 1) * 4;
    const int brow  = tid >> 5;
    const int bcol4 = (tid & 31) * 4;

    const float* Aptr = &A[(size_t)(bm + arow) * K + acol4];
    const float* Bptr = &Bm[(size_t)brow * NOUT + bn + bcol4];

    // prologue: tile 0 -> buffer 0 (A stored as duplicated pairs via STS.64)
    {
        float4 av = *(const float4*)Aptr;
        float4 bv = *(const float4*)Bptr;
        *(unsigned long long*)&As[0][acol4 + 0][2 * arow] = pack2(av.x);
        *(unsigned long long*)&As[0][acol4 + 1][2 * arow] = pack2(av.y);
        *(unsigned long long*)&As[0][acol4 + 2][2 * arow] = pack2(av.z);
        *(unsigned long long*)&As[0][acol4 + 3][2 * arow] = pack2(av.w);
        *(float4*)&Bs[0][brow][bcol4] = bv;
    }
    __syncthreads();

    int buf = 0;
    for (int k0 = 0; k0 < K; k0 += 8) {
        // prefetch next tile into registers while computing on current smem
        float4 av2, bv2;
        const bool more = (k0 + 8 < K);
        if (more) {
            av2 = *(const float4*)(Aptr + k0 + 8);
            bv2 = *(const float4*)(Bptr + (size_t)(k0 + 8) * NOUT);
        }
#pragma unroll
        for (int k = 0; k < 8; k++) {
            ulonglong2 a01 = *(const ulonglong2*)&As[buf][k][2 * (ty * 4)];
            ulonglong2 a23 = *(const ulonglong2*)&As[buf][k][2 * (ty * 4) + 4];
            ulonglong2 a45 = *(const ulonglong2*)&As[buf][k][2 * (64 + ty * 4)];
            ulonglong2 a67 = *(const ulonglong2*)&As[buf][k][2 * (64 + ty * 4) + 4];
            ulonglong2 b01 = *(const ulonglong2*)&Bs[buf][k][tx * 4];
            ulonglong2 b23 = *(const ulonglong2*)&Bs[buf][k][64 + tx * 4];
            unsigned long long ap[8] = {a01.x, a01.y, a23.x, a23.y,
                                        a45.x, a45.y, a67.x, a67.y};
            unsigned long long bp[4] = {b01.x, b01.y, b23.x, b23.y};
#pragma unroll
            for (int ii = 0; ii < 8; ii++) {
                fma2(acc2[ii][0], ap[ii], bp[0]);
                fma2(acc2[ii][1], ap[ii], bp[1]);
                fma2(acc2[ii][2], ap[ii], bp[2]);
                fma2(acc2[ii][3], ap[ii], bp[3]);
            }
        }
        if (more) {
            int nb = buf ^ 1;
            *(unsigned long long*)&As[nb][acol4 + 0][2 * arow] = pack2(av2.x);
            *(unsigned long long*)&As[nb][acol4 + 1][2 * arow] = pack2(av2.y);
            *(unsigned long long*)&As[nb][acol4 + 2][2 * arow] = pack2(av2.z);
            *(unsigned long long*)&As[nb][acol4 + 3][2 * arow] = pack2(av2.w);
            *(float4*)&Bs[nb][brow][bcol4] = bv2;
        }
        __syncthreads();
        buf ^= 1;
    }

    // epilogue: acc2[ii][jp] holds column-pair jp -> 2 scalars each
#pragma unroll
    for (int ii = 0; ii < 8; ii++) {
        int r = bm + ((ii < 4) ? (ty * 4 + ii) : (60 + ty * 4 + ii));
        int bwin = r / NT_;
        int n    = r - bwin * NT_;
#pragma unroll
        for (int jp = 0; jp < 4; jp++) {
            float vals[2] = {lo2(acc2[ii][jp]), hi2(acc2[ii][jp])};
#pragma unroll
            for (int half = 0; half < 2; half++) {
                int c = bn + ((jp < 2) ? (tx * 4 + jp * 2 + half)
                                       : (64 + tx * 4 + (jp - 2) * 2 + half));
                float v = vals[half] + bias[c];
                if (QKV) {
                    int part = c / DIM_;
                    int rem  = c - part * DIM_;
                    int h = rem >> 5;
                    int d = rem & 31;
                    size_t idx = (((size_t)bwin * HEADS_ + h) * NT_ + n) * HD_ + d;
                    if (part == 0)      g_q[idx] = v * 0.17677669529663687f; // 1/sqrt(32)
                    else if (part == 1) g_k[idx] = v;
                    else                g_v[idx] = v;
                } else {
                    out[(size_t)r * NOUT + c] = v;
                }
            }
        }
    }
}

// ---------------------------------------------------------------------------
// Fused attention: 2 CTAs per (window b, head h), each owning 72 query rows.
// 256 threads. smem ~100 KB -> 2 CTAs/SM.
// smem: Qt[32][76] (transposed, this half), Kt[32][148] (all keys),
//       Vs[144][32], S[72][149], Sb[18][144] (deduped bias plane)
// ---------------------------------------------------------------------------
#define ATTN_THREADS 256
#define IH_ 72                 // rows per CTA half
#define QT_STRIDE 76
#define KT_STRIDE 148
#define S_STRIDE  149
#define ATTN_SMEM_FLOATS (32*QT_STRIDE + 32*KT_STRIDE + NT_*HD_ + IH_*S_STRIDE + 18*NT_)
#define ATTN_SMEM_BYTES  (ATTN_SMEM_FLOATS * 4)

__global__ __launch_bounds__(ATTN_THREADS) void attn_kernel(const float* __restrict__ mask,
                                                            const float* __restrict__ bias_table,
                                                            const int*   __restrict__ pos_index)
{
    extern __shared__ float smem[];
    float* Qt = smem;                         // 32 x 76
    float* Kt = Qt + 32 * QT_STRIDE;          // 32 x 148
    float* Vs = Kt + 32 * KT_STRIDE;          // 144 x 32
    float* S  = Vs + NT_ * HD_;               // 72 x 149
    float* Sb = S  + IH_ * S_STRIDE;          // 18 x 144 deduped bias plane

    const int blk = blockIdx.x;
    const int hf  = blk & 1;                  // which i-half
    const int bh  = blk >> 1;
    const int b   = bh / HEADS_;
    const int h   = bh - b * HEADS_;
    const int tid = threadIdx.x;

    const float* Qg = g_q + (size_t)bh * NT_ * HD_ + (size_t)hf * IH_ * HD_;
    const float* Kg = g_k + (size_t)bh * NT_ * HD_;
    const float* Vg = g_v + (size_t)bh * NT_ * HD_;

    const int b5  = b >> 5;     // which tile repeat of position_index
    const int t32 = b & 31;     // type-of-window index into bias_table
    const int w   = b & 7;      // mask window
    const float* maskw = mask + (size_t)w * NN_ + (size_t)hf * IH_ * NT_;

    // load + transpose Q (this half) and K (all); V natural
    for (int idx = tid; idx < NT_ * HD_; idx += ATTN_THREADS) {
        int n = idx >> 5, d = idx & 31;
        Kt[d * KT_STRIDE + n] = Kg[idx];
        Vs[idx] = Vg[idx];
        if (idx < IH_ * HD_)
            Qt[d * QT_STRIDE + n] = Qg[idx];
    }
    // deduped bias gather: bias(i,j) depends only on (i mod 18, j).
    // p = ((i%18)*144 + j)*8 + b5 ; Sb[idx] = table[pos_index[p]][t32][h]
    for (int idx = tid; idx < 18 * NT_; idx += ATTN_THREADS) {
        int row = pos_index[idx * 8 + b5];
        Sb[idx] = bias_table[(size_t)row * (TOW_ * HEADS_) + t32 * HEADS_ + h];
    }
    __syncthreads();

    // --- scores: 18x36 grid of 4x4 tiles (q broadcast-packed, k natural pairs)
    for (int t = tid; t < (IH_ / 4) * 36; t += ATTN_THREADS) {
        int i0 = (t / 36) * 4;                // local row
        int j0 = (t % 36) * 4;
        unsigned long long acc2[4][2];
#pragma unroll
        for (int r = 0; r < 4; r++) { acc2[r][0] = 0ull; acc2[r][1] = 0ull; }
#pragma unroll
        for (int d = 0; d < 32; d++) {
            float4 qa = *(const float4*)&Qt[d * QT_STRIDE + i0];
            ulonglong2 kb = *(const ulonglong2*)&Kt[d * KT_STRIDE + j0];
            unsigned long long q0 = pack2(qa.x), q1 = pack2(qa.y);
            unsigned long long q2 = pack2(qa.z), q3 = pack2(qa.w);
            fma2(acc2[0][0], q0, kb.x); fma2(acc2[0][1], q0, kb.y);
            fma2(acc2[1][0], q1, kb.x); fma2(acc2[1][1], q1, kb.y);
            fma2(acc2[2][0], q2, kb.x); fma2(acc2[2][1], q2, kb.y);
            fma2(acc2[3][0], q3, kb.x); fma2(acc2[3][1], q3, kb.y);
        }
#pragma unroll
        for (int r = 0; r < 4; r++) {
            int i = i0 + r;                   // local; global gi = hf*72 + i
            int im18 = i % 18;                // 72 % 18 == 0 so gi%18 == i%18
            const float* sbrow = &Sb[im18 * NT_];
            const float* mrow  = &maskw[i * NT_];
            float sv[4] = {lo2(acc2[r][0]), hi2(acc2[r][0]),
                           lo2(acc2[r][1]), hi2(acc2[r][1])};
#pragma unroll
            for (int c = 0; c < 4; c++) {
                int j = j0 + c;
                S[i * S_STRIDE + j] = sv[c] + sbrow[j] + mrow[j];
            }
        }
    }
    __syncthreads();

    // --- softmax: 8 warps, 9 rows each ---
    const int warp = tid >> 5, lane = tid & 31;
    for (int i = warp; i < IH_; i += (ATTN_THREADS / 32)) {
        float* Srow = &S[i * S_STRIDE];
        float mx = -1e30f;
        for (int c = lane; c < NT_; c += 32) mx = fmaxf(mx, Srow[c]);
#pragma unroll
        for (int o = 16; o; o >>= 1) mx = fmaxf(mx, __shfl_xor_sync(0xffffffffu, mx, o));
        float sum = 0.f;
        for (int c = lane; c < NT_; c += 32) {
            float e = __expf(Srow[c] - mx);
            Srow[c] = e;
            sum += e;
        }
#pragma unroll
        for (int o = 16; o; o >>= 1) sum += __shfl_xor_sync(0xffffffffu, sum, o);
        float inv = 1.f / sum;
        for (int c = lane; c < NT_; c += 32) Srow[c] *= inv;
    }
    __syncthreads();

    // --- PV: 36 i-tiles x 8 d-tiles of 2x4 (p broadcast, v pairs) ---
    float* Og = g_att + (size_t)b * NT_ * DIM_ + (size_t)hf * IH_ * DIM_ + h * HD_;
    for (int t = tid; t < (IH_ / 2) * 8; t += ATTN_THREADS) {
        int i0 = (t >> 3) * 2;                // local
        int d0 = (t & 7) * 4;
        unsigned long long acc2[2][2];
        acc2[0][0] = 0ull; acc2[0][1] = 0ull;
        acc2[1][0] = 0ull; acc2[1][1] = 0ull;
        for (int j = 0; j < NT_; j++) {
            ulonglong2 vv = *(const ulonglong2*)&Vs[j * HD_ + d0];
            unsigned long long p0 = pack2(S[(i0 + 0) * S_STRIDE + j]);
            unsigned long long p1 = pack2(S[(i0 + 1) * S_STRIDE + j]);
            fma2(acc2[0][0], p0, vv.x); fma2(acc2[0][1], p0, vv.y);
            fma2(acc2[1][0], p1, vv.x); fma2(acc2[1][1], p1, vv.y);
        }
#pragma unroll
        for (int r = 0; r < 2; r++) {
            float4 o4 = make_float4(lo2(acc2[r][0]), hi2(acc2[r][0]),
                                    lo2(acc2[r][1]), hi2(acc2[r][1]));
            *(float4*)&Og[(size_t)(i0 + r) * DIM_ + d0] = o4;
        }
    }
}

// ---------------------------------------------------------------------------
extern "C" void kernel_launch(void* const* d_in, const int* in_sizes, int n_in,
                              void* d_out, int out_size)
{
    const float* x          = (const float*)d_in[0];
    const float* mask       = (const float*)d_in[1];
    const float* w_qkv      = (const float*)d_in[2];
    const float* b_qkv      = (const float*)d_in[3];
    const float* w_out      = (const float*)d_in[4];
    const float* b_out      = (const float*)d_in[5];
    const float* bias_table = (const float*)d_in[6];
    const int*   pos_index  = (const int*)d_in[7];
    float* out = (float*)d_out;

    // idempotent, deterministic: safe to call every launch (not a stream op)
    cudaFuncSetAttribute(attn_kernel, cudaFuncAttributeMaxDynamicSharedMemorySize,
                         ATTN_SMEM_BYTES);

    // Stage A: QKV projection
    sgemm128<3 * DIM_, true><<<dim3((3 * DIM_) / 128, MTOT_ / 128), 256>>>(
        x, w_qkv, b_qkv, nullptr);

    // Stage B: fused attention, 2 CTAs per (window, head)
    attn_kernel<<<BW_ * HEADS_ * 2, ATTN_THREADS, ATTN_SMEM_BYTES>>>(
        mask, bias_table, pos_index);

    // Stage C: output projection
    sgemm128<DIM_, false><<<dim3(DIM_ / 128, MTOT_ / 128), 256>>>(
        nullptr, w_out, b_out, out);
}

// round 11
// speedup vs baseline: 1.2736x; 1.2401x over previous
#include <cuda_runtime.h>

// ---------------------------------------------------------------------------
// EarthAttention3D  (Bw=256, N=144, DIM=384, H=12, HD=32)
// Stage A: QKV GEMM  (36864x384 @ 384x1152) -> Q(scaled),K,V in (b,h,n,d)
// Stage B: attention, 2 CTAs per (b,h) (i-halves of 72 rows), 288 threads:
//          deduped bias plane in smem; scores = 6x6 tiles (exactly 1/thread);
//          softmax 8 rows/warp; PV exactly 1 task/thread (paired-j S loads)
// Stage C: out GEMM  (36864x384 @ 384x384) + bias -> d_out
// All inner products use Blackwell packed fma.rn.f32x2 (2 fp32 FMA / issue).
// GEMM: A broadcast via register packs (measured better than duplicated smem).
// ---------------------------------------------------------------------------

#define BW_    256
#define NT_    144
#define DIM_   384
#define HEADS_ 12
#define HD_    32
#define NN_    (NT_*NT_)      // 20736
#define TOW_   32
#define MTOT_  (BW_*NT_)      // 36864

// scratch (device globals; allocation in kernel_launch is forbidden)
__device__ float g_q[(size_t)BW_*HEADS_*NT_*HD_];
__device__ float g_k[(size_t)BW_*HEADS_*NT_*HD_];
__device__ float g_v[(size_t)BW_*HEADS_*NT_*HD_];
__device__ float g_att[(size_t)BW_*NT_*DIM_];

// ---- packed f32x2 helpers (sm_103a) ---------------------------------------
__device__ __forceinline__ unsigned long long pack2(float x) {
    unsigned long long r;
    asm("mov.b64 %0, {%1, %1};" : "=l"(r) : "f"(x));
    return r;
}
__device__ __forceinline__ void fma2(unsigned long long& d,
                                     unsigned long long a,
                                     unsigned long long b) {
    asm("fma.rn.f32x2 %0, %1, %2, %0;" : "+l"(d) : "l"(a), "l"(b));
}
__device__ __forceinline__ unsigned long long add2v(unsigned long long a,
                                                    unsigned long long b) {
    unsigned long long r;
    asm("add.rn.f32x2 %0, %1, %2;" : "=l"(r) : "l"(a), "l"(b));
    return r;
}
__device__ __forceinline__ float lo2(unsigned long long v) {
    return __uint_as_float((unsigned)v);
}
__device__ __forceinline__ float hi2(unsigned long long v) {
    return __uint_as_float((unsigned)(v >> 32));
}

// ---------------------------------------------------------------------------
// 128x128x8 register-tiled SGEMM, 256 threads, 8x8 microtile per thread.
// Double-buffered smem + register prefetch: one barrier per K-tile.
// ---------------------------------------------------------------------------
template<int NOUT, bool QKV>
__global__ __launch_bounds__(256) void sgemm128(const float* __restrict__ A_in,
                                                const float* __restrict__ Bm,
                                                const float* __restrict__ bias,
                                                float* __restrict__ out)
{
    __shared__ float As[2][8][132];
    __shared__ float Bs[2][8][132];
    const int K = DIM_;
    const float* A = QKV ? A_in : g_att;

    const int bm = blockIdx.y * 128;
    const int bn = blockIdx.x * 128;
    const int tid = threadIdx.x;
    const int tx = tid & 15, ty = tid >> 4;

    unsigned long long acc2[8][4];
#pragma unroll
    for (int i = 0; i < 8; i++)
#pragma unroll
        for (int j = 0; j < 4; j++) acc2[i][j] = 0ull;

    const int arow  = tid >> 1;
    const int acol4 = (tid & 1) * 4;
    const int brow  = tid >> 5;
    const int bcol4 = (tid & 31) * 4;

    const float* Aptr = &A[(size_t)(bm + arow) * K + acol4];
    const float* Bptr = &Bm[(size_t)brow * NOUT + bn + bcol4];

    // prologue: tile 0 -> buffer 0
    {
        float4 av = *(const float4*)Aptr;
        float4 bv = *(const float4*)Bptr;
        As[0][acol4 + 0][arow] = av.x;
        As[0][acol4 + 1][arow] = av.y;
        As[0][acol4 + 2][arow] = av.z;
        As[0][acol4 + 3][arow] = av.w;
        *(float4*)&Bs[0][brow][bcol4] = bv;
    }
    __syncthreads();

    int buf = 0;
    for (int k0 = 0; k0 < K; k0 += 8) {
        float4 av2, bv2;
        const bool more = (k0 + 8 < K);
        if (more) {
            av2 = *(const float4*)(Aptr + k0 + 8);
            bv2 = *(const float4*)(Bptr + (size_t)(k0 + 8) * NOUT);
        }
#pragma unroll
        for (int k = 0; k < 8; k++) {
            float4 a0 = *(const float4*)&As[buf][k][ty * 4];
            float4 a1 = *(const float4*)&As[buf][k][64 + ty * 4];
            ulonglong2 b01 = *(const ulonglong2*)&Bs[buf][k][tx * 4];
            ulonglong2 b23 = *(const ulonglong2*)&Bs[buf][k][64 + tx * 4];
            unsigned long long ap[8];
            ap[0] = pack2(a0.x); ap[1] = pack2(a0.y);
            ap[2] = pack2(a0.z); ap[3] = pack2(a0.w);
            ap[4] = pack2(a1.x); ap[5] = pack2(a1.y);
            ap[6] = pack2(a1.z); ap[7] = pack2(a1.w);
            unsigned long long bp[4] = {b01.x, b01.y, b23.x, b23.y};
#pragma unroll
            for (int ii = 0; ii < 8; ii++) {
                fma2(acc2[ii][0], ap[ii], bp[0]);
                fma2(acc2[ii][1], ap[ii], bp[1]);
                fma2(acc2[ii][2], ap[ii], bp[2]);
                fma2(acc2[ii][3], ap[ii], bp[3]);
            }
        }
        if (more) {
            int nb = buf ^ 1;
            As[nb][acol4 + 0][arow] = av2.x;
            As[nb][acol4 + 1][arow] = av2.y;
            As[nb][acol4 + 2][arow] = av2.z;
            As[nb][acol4 + 3][arow] = av2.w;
            *(float4*)&Bs[nb][brow][bcol4] = bv2;
        }
        __syncthreads();
        buf ^= 1;
    }

    // epilogue: acc2[ii][jp] holds column-pair jp -> 2 scalars each
#pragma unroll
    for (int ii = 0; ii < 8; ii++) {
        int r = bm + ((ii < 4) ? (ty * 4 + ii) : (60 + ty * 4 + ii));
        int bwin = r / NT_;
        int n    = r - bwin * NT_;
#pragma unroll
        for (int jp = 0; jp < 4; jp++) {
            float vals[2] = {lo2(acc2[ii][jp]), hi2(acc2[ii][jp])};
#pragma unroll
            for (int half = 0; half < 2; half++) {
                int c = bn + ((jp < 2) ? (tx * 4 + jp * 2 + half)
                                       : (64 + tx * 4 + (jp - 2) * 2 + half));
                float v = vals[half] + bias[c];
                if (QKV) {
                    int part = c / DIM_;
                    int rem  = c - part * DIM_;
                    int h = rem >> 5;
                    int d = rem & 31;
                    size_t idx = (((size_t)bwin * HEADS_ + h) * NT_ + n) * HD_ + d;
                    if (part == 0)      g_q[idx] = v * 0.17677669529663687f; // 1/sqrt(32)
                    else if (part == 1) g_k[idx] = v;
                    else                g_v[idx] = v;
                } else {
                    out[(size_t)r * NOUT + c] = v;
                }
            }
        }
    }
}

// ---------------------------------------------------------------------------
// Fused attention: 2 CTAs per (window b, head h), each owning 72 query rows.
// 288 threads (9 warps). smem ~98 KB -> 2 CTAs/SM.
// smem: Qt[32][76] (transposed, this half), Kt[32][148] (all keys),
//       Vs[144][32], S[72][150], Sb[18][144] (deduped bias plane)
// ---------------------------------------------------------------------------
#define ATTN_THREADS 288
#define IH_ 72                 // rows per CTA half
#define QT_STRIDE 76
#define KT_STRIDE 148
#define S_STRIDE  150
#define ATTN_SMEM_FLOATS (32*QT_STRIDE + 32*KT_STRIDE + NT_*HD_ + IH_*S_STRIDE + 18*NT_)
#define ATTN_SMEM_BYTES  (ATTN_SMEM_FLOATS * 4)

__global__ __launch_bounds__(ATTN_THREADS) void attn_kernel(const float* __restrict__ mask,
                                                            const float* __restrict__ bias_table,
                                                            const int*   __restrict__ pos_index)
{
    extern __shared__ float smem[];
    float* Qt = smem;                         // 32 x 76
    float* Kt = Qt + 32 * QT_STRIDE;          // 32 x 148
    float* Vs = Kt + 32 * KT_STRIDE;          // 144 x 32
    float* S  = Vs + NT_ * HD_;               // 72 x 150
    float* Sb = S  + IH_ * S_STRIDE;          // 18 x 144 deduped bias plane

    const int blk = blockIdx.x;
    const int hf  = blk & 1;                  // which i-half
    const int bh  = blk >> 1;
    const int b   = bh / HEADS_;
    const int h   = bh - b * HEADS_;
    const int tid = threadIdx.x;

    const float* Qg = g_q + (size_t)bh * NT_ * HD_ + (size_t)hf * IH_ * HD_;
    const float* Kg = g_k + (size_t)bh * NT_ * HD_;
    const float* Vg = g_v + (size_t)bh * NT_ * HD_;

    const int b5  = b >> 5;     // which tile repeat of position_index
    const int t32 = b & 31;     // type-of-window index into bias_table
    const int w   = b & 7;      // mask window
    const float* maskw = mask + (size_t)w * NN_ + (size_t)hf * IH_ * NT_;

    // load + transpose Q (this half) and K (all); V natural (4608/288 = 16)
    for (int idx = tid; idx < NT_ * HD_; idx += ATTN_THREADS) {
        int n = idx >> 5, d = idx & 31;
        Kt[d * KT_STRIDE + n] = Kg[idx];
        Vs[idx] = Vg[idx];
        if (idx < IH_ * HD_)
            Qt[d * QT_STRIDE + n] = Qg[idx];
    }
    // deduped bias gather: bias(i,j) depends only on (i mod 18, j). 2592/288 = 9.
    for (int idx = tid; idx < 18 * NT_; idx += ATTN_THREADS) {
        int row = pos_index[idx * 8 + b5];
        Sb[idx] = bias_table[(size_t)row * (TOW_ * HEADS_) + t32 * HEADS_ + h];
    }
    __syncthreads();

    // --- scores: 12x24 grid of 6x6 tiles = 288 tasks, exactly 1 per thread ---
    {
        const int i0 = (tid / 24) * 6;        // local row (0..66, even)
        const int j0 = (tid % 24) * 6;        // col (0..138, even)
        unsigned long long acc2[6][3];
#pragma unroll
        for (int r = 0; r < 6; r++)
#pragma unroll
            for (int c = 0; c < 3; c++) acc2[r][c] = 0ull;

#pragma unroll 8
        for (int d = 0; d < 32; d++) {
            const float* qrow = &Qt[d * QT_STRIDE + i0];
            const float* krow = &Kt[d * KT_STRIDE + j0];
            float2 qa = *(const float2*)&qrow[0];
            float2 qb = *(const float2*)&qrow[2];
            float2 qc = *(const float2*)&qrow[4];
            unsigned long long k0 = *(const unsigned long long*)&krow[0];
            unsigned long long k1 = *(const unsigned long long*)&krow[2];
            unsigned long long k2 = *(const unsigned long long*)&krow[4];
            unsigned long long q[6];
            q[0] = pack2(qa.x); q[1] = pack2(qa.y);
            q[2] = pack2(qb.x); q[3] = pack2(qb.y);
            q[4] = pack2(qc.x); q[5] = pack2(qc.y);
#pragma unroll
            for (int r = 0; r < 6; r++) {
                fma2(acc2[r][0], q[r], k0);
                fma2(acc2[r][1], q[r], k1);
                fma2(acc2[r][2], q[r], k2);
            }
        }
        const int im18base = i0 % 18;         // i0%18 in {0,6,12}; +r<=17, no wrap
#pragma unroll
        for (int r = 0; r < 6; r++) {
            int i = i0 + r;
            const float* sbrow = &Sb[(im18base + r) * NT_ + j0];
            const float* mrow  = &maskw[(size_t)i * NT_ + j0];
            float* srow = &S[i * S_STRIDE + j0];
#pragma unroll
            for (int c = 0; c < 3; c++) {
                unsigned long long bm2 = add2v(*(const unsigned long long*)&sbrow[2 * c],
                                               *(const unsigned long long*)&mrow[2 * c]);
                *(unsigned long long*)&srow[2 * c] = add2v(acc2[r][c], bm2);
            }
        }
    }
    __syncthreads();

    // --- softmax: 9 warps, exactly 8 rows each ---
    const int warp = tid >> 5, lane = tid & 31;
    for (int i = warp; i < IH_; i += (ATTN_THREADS / 32)) {
        float* Srow = &S[i * S_STRIDE];
        float mx = -1e30f;
        for (int c = lane; c < NT_; c += 32) mx = fmaxf(mx, Srow[c]);
#pragma unroll
        for (int o = 16; o; o >>= 1) mx = fmaxf(mx, __shfl_xor_sync(0xffffffffu, mx, o));
        float sum = 0.f;
        for (int c = lane; c < NT_; c += 32) {
            float e = __expf(Srow[c] - mx);
            Srow[c] = e;
            sum += e;
        }
#pragma unroll
        for (int o = 16; o; o >>= 1) sum += __shfl_xor_sync(0xffffffffu, sum, o);
        float inv = 1.f / sum;
        for (int c = lane; c < NT_; c += 32) Srow[c] *= inv;
    }
    __syncthreads();

    // --- PV: 36 i-tiles x 8 d-tiles of 2x4 = 288 tasks, exactly 1/thread ---
    // S rows read as float2 over paired j (8B-aligned: S_STRIDE even, j even).
    float* Og = g_att + (size_t)b * NT_ * DIM_ + (size_t)hf * IH_ * DIM_ + h * HD_;
    {
        const int t = tid;
        const int i0 = (t >> 3) * 2;          // local
        const int d0 = (t & 7) * 4;
        unsigned long long acc2[2][2];
        acc2[0][0] = 0ull; acc2[0][1] = 0ull;
        acc2[1][0] = 0ull; acc2[1][1] = 0ull;
        const float* s0 = &S[(i0 + 0) * S_STRIDE];
        const float* s1 = &S[(i0 + 1) * S_STRIDE];
        for (int j = 0; j < NT_; j += 2) {
            ulonglong2 va = *(const ulonglong2*)&Vs[j * HD_ + d0];
            ulonglong2 vb = *(const ulonglong2*)&Vs[(j + 1) * HD_ + d0];
            float2 p0p = *(const float2*)&s0[j];
            float2 p1p = *(const float2*)&s1[j];
            unsigned long long p0a = pack2(p0p.x), p0b = pack2(p0p.y);
            unsigned long long p1a = pack2(p1p.x), p1b = pack2(p1p.y);
            fma2(acc2[0][0], p0a, va.x); fma2(acc2[0][1], p0a, va.y);
            fma2(acc2[1][0], p1a, va.x); fma2(acc2[1][1], p1a, va.y);
            fma2(acc2[0][0], p0b, vb.x); fma2(acc2[0][1], p0b, vb.y);
            fma2(acc2[1][0], p1b, vb.x); fma2(acc2[1][1], p1b, vb.y);
        }
#pragma unroll
        for (int r = 0; r < 2; r++) {
            float4 o4 = make_float4(lo2(acc2[r][0]), hi2(acc2[r][0]),
                                    lo2(acc2[r][1]), hi2(acc2[r][1]));
            *(float4*)&Og[(size_t)(i0 + r) * DIM_ + d0] = o4;
        }
    }
}

// ---------------------------------------------------------------------------
extern "C" void kernel_launch(void* const* d_in, const int* in_sizes, int n_in,
                              void* d_out, int out_size)
{
    const float* x          = (const float*)d_in[0];
    const float* mask       = (const float*)d_in[1];
    const float* w_qkv      = (const float*)d_in[2];
    const float* b_qkv      = (const float*)d_in[3];
    const float* w_out      = (const float*)d_in[4];
    const float* b_out      = (const float*)d_in[5];
    const float* bias_table = (const float*)d_in[6];
    const int*   pos_index  = (const int*)d_in[7];
    float* out = (float*)d_out;

    // idempotent, deterministic: safe to call every launch (not a stream op)
    cudaFuncSetAttribute(attn_kernel, cudaFuncAttributeMaxDynamicSharedMemorySize,
                         ATTN_SMEM_BYTES);

    // Stage A: QKV projection
    sgemm128<3 * DIM_, true><<<dim3((3 * DIM_) / 128, MTOT_ / 128), 256>>>(
        x, w_qkv, b_qkv, nullptr);

    // Stage B: fused attention, 2 CTAs per (window, head)
    attn_kernel<<<BW_ * HEADS_ * 2, ATTN_THREADS, ATTN_SMEM_BYTES>>>(
        mask, bias_table, pos_index);

    // Stage C: output projection
    sgemm128<DIM_, false><<<dim3(DIM_ / 128, MTOT_ / 128), 256>>>(
        nullptr, w_out, b_out, out);
}